// round 3
// baseline (speedup 1.0000x reference)
#include <cuda_runtime.h>

// Problem constants
#define BATCH 16
#define CH    256     // CIN == COUT == 256
#define HH    64
#define WW    64
#define TY    16      // output rows per block tile

// ---------------------------------------------------------------------------
// Scratch (device globals — no runtime allocation allowed)
// ---------------------------------------------------------------------------
__device__ float g_scale[CH * CH];      // cumprod(relu(weight)) with row0 = 1
__device__ int   g_cin  [CH * CH];      // per-cout compacted list of nonzero cin
__device__ float g_w    [CH * CH * 12]; // pre-scaled 3x3 weights, padded to 12 floats
__device__ int   g_count[CH];           // nonzero cin count per cout

// ---------------------------------------------------------------------------
// K1a: per-cin-column sequential cumprod of relu(weight), row 0 forced to 1.
// One block, 256 threads (thread = cin). 255 dependent multiplies, ~2us.
// ---------------------------------------------------------------------------
__global__ void scale_kernel(const float* __restrict__ weight) {
    int cin = threadIdx.x;
    float p = 1.0f;
    g_scale[cin] = 1.0f;                      // co = 0: no scaling
    for (int co = 1; co < CH; ++co) {
        p *= fmaxf(weight[co * CH + cin], 0.0f);
        g_scale[co * CH + cin] = p;           // exact 0 once any factor <= 0
    }
}

// ---------------------------------------------------------------------------
// K1b: deterministic compaction (ballot + popc prefix — no atomics, so slot
// order and therefore fp accumulation order are identical on every replay).
// Also folds the scale into the 3x3 weights, padded to 12 floats so the conv
// kernel can fetch them as 3x LDG.128.
// ---------------------------------------------------------------------------
__global__ void compact_kernel(const float* __restrict__ conv_w) {
    int co  = blockIdx.x;
    int cin = threadIdx.x;
    float sc = g_scale[co * CH + cin];
    bool active = (sc != 0.0f);
    unsigned mask = __ballot_sync(0xffffffffu, active);
    int lane = cin & 31, warp = cin >> 5;
    __shared__ int wcnt[8];
    if (lane == 0) wcnt[warp] = __popc(mask);
    __syncthreads();
    int base = 0;
    #pragma unroll
    for (int i = 0; i < 8; i++)
        if (i < warp) base += wcnt[i];
    if (active) {
        int slot = base + __popc(mask & ((1u << lane) - 1u));
        g_cin[co * CH + slot] = cin;
        const float* ws = conv_w + (size_t)(co * CH + cin) * 9;
        float*       wd = g_w    + (size_t)(co * CH + slot) * 12;
        #pragma unroll
        for (int k = 0; k < 9; k++) wd[k] = ws[k] * sc;
        wd[9] = 0.0f; wd[10] = 0.0f; wd[11] = 0.0f;
    }
    if (cin == 0) {
        int t = 0;
        #pragma unroll
        for (int i = 0; i < 8; i++) t += wcnt[i];
        g_count[co] = t;
    }
}

// ---------------------------------------------------------------------------
// K2: direct 3x3 conv over the compacted channel list.
// grid = (4 y-tiles, 256 cout, 16 batch), 256 threads.
// Thread (tid) -> output column cx = tid&63, output rows ty..ty+3 of the tile
// (ty = (tid>>6)*4). Smem tile: (TY+2) x (WW+2); halo columns (x=-1, x=64)
// are always outside the image -> zeroed once, never rewritten.
// Inner body per channel-slot: 18 LDS + 36 FFMA (+ 3 uniform LDG.128 weights).
// Empty couts (~240 of 256) degenerate to a pure bias store.
// ---------------------------------------------------------------------------
__global__ __launch_bounds__(256) void conv_kernel(const float* __restrict__ in,
                                                   const float* __restrict__ bias,
                                                   float* __restrict__ out) {
    int co  = blockIdx.y;
    int b   = blockIdx.z;
    int y0  = blockIdx.x * TY;
    int tid = threadIdx.x;
    int cx  = tid & 63;
    int ty  = (tid >> 6) << 2;

    __shared__ float s_tile[TY + 2][WW + 2];

    // Zero the permanent halo columns (input x = -1 and x = 64).
    if (tid < 2 * (TY + 2)) {
        int r = tid >> 1;
        int c = (tid & 1) ? (WW + 1) : 0;
        s_tile[r][c] = 0.0f;
    }

    int cnt = g_count[co];
    float acc0 = 0.0f, acc1 = 0.0f, acc2 = 0.0f, acc3 = 0.0f;

    for (int s = 0; s < cnt; ++s) {
        int cin = g_cin[co * CH + s];
        const float4* wp = reinterpret_cast<const float4*>(g_w + (size_t)(co * CH + s) * 12);
        float4 w0 = wp[0];
        float4 w1 = wp[1];
        float4 w2 = wp[2];
        const float* plane = in + (((size_t)b * CH + cin) << 12);  // 64*64 plane

        __syncthreads();   // previous iteration's readers done before refill
        #pragma unroll
        for (int i = 0; i < 5; i++) {
            int idx = tid + i * 256;
            if (idx < (TY + 2) * WW) {
                int r  = idx >> 6;
                int c  = idx & 63;
                int gy = y0 - 1 + r;
                s_tile[r][c + 1] = (gy >= 0 && gy < HH) ? plane[(gy << 6) + c] : 0.0f;
            }
        }
        __syncthreads();

        // 6-row x 3-col register window for this thread's 4-row output strip.
        float v[6][3];
        #pragma unroll
        for (int r = 0; r < 6; r++)
            #pragma unroll
            for (int d = 0; d < 3; d++)
                v[r][d] = s_tile[ty + r][cx + d];

        float wk[9] = {w0.x, w0.y, w0.z, w0.w, w1.x, w1.y, w1.z, w1.w, w2.x};
        #pragma unroll
        for (int dy = 0; dy < 3; dy++) {
            #pragma unroll
            for (int d = 0; d < 3; d++) {
                float wv = wk[dy * 3 + d];
                acc0 = fmaf(wv, v[0 + dy][d], acc0);
                acc1 = fmaf(wv, v[1 + dy][d], acc1);
                acc2 = fmaf(wv, v[2 + dy][d], acc2);
                acc3 = fmaf(wv, v[3 + dy][d], acc3);
            }
        }
    }

    float bv = __ldg(bias + co);
    size_t obase = (((size_t)b * CH + co) << 12) + (size_t)((y0 + ty) << 6) + (size_t)cx;
    out[obase]          = acc0 + bv;
    out[obase + WW]     = acc1 + bv;
    out[obase + 2 * WW] = acc2 + bv;
    out[obase + 3 * WW] = acc3 + bv;
}

// ---------------------------------------------------------------------------
// Entry point. Inputs (metadata order): input, conv_w, conv_b, weight.
// Three plain launches: graph-capturable, allocation-free, deterministic.
// ---------------------------------------------------------------------------
extern "C" void kernel_launch(void* const* d_in, const int* in_sizes, int n_in,
                              void* d_out, int out_size) {
    (void)in_sizes; (void)n_in; (void)out_size;
    const float* input  = (const float*)d_in[0];
    const float* conv_w = (const float*)d_in[1];
    const float* conv_b = (const float*)d_in[2];
    const float* weight = (const float*)d_in[3];
    float* out = (float*)d_out;

    scale_kernel<<<1, 256>>>(weight);
    compact_kernel<<<CH, 256>>>(conv_w);
    dim3 grid(HH / TY, CH, BATCH);
    conv_kernel<<<grid, 256>>>(input, conv_b, out);
}

// round 4
// speedup vs baseline: 2.2965x; 2.2965x over previous
#include <cuda_runtime.h>

// Problem constants
#define BATCH 16
#define CH    256     // CIN == COUT == 256
#define HH    64
#define WW    64
#define TY    16      // output rows per block tile
#define TILE_ELEMS ((TY + 2) * WW)   // 1152 interior loads per tile

// Split-cout static schedule: co0 -> 16 chunks, co1 -> 8, co2 -> 4, co3 -> 2,
// co4 -> 2, co5..255 -> 1 chunk each.  grid.y = 32 + 251 = 283.
#define NSPLIT_ENTRIES 32
#define GRID_Y 283

// ---------------------------------------------------------------------------
// Scratch (device globals — no runtime allocation allowed)
// ---------------------------------------------------------------------------
__device__ float g_scale[CH * CH];      // cumprod(relu(weight)) with row0 = 1
__device__ int   g_cin  [CH * CH];      // per-cout compacted nonzero cin list
__device__ float g_w    [CH * CH * 12]; // pre-scaled 3x3 weights, padded to 12
__device__ int   g_count[CH];           // nonzero cin count per cout
__device__ float g_part [NSPLIT_ENTRIES * BATCH * HH * WW];  // 8 MB partials

// ---------------------------------------------------------------------------
// K1a: parallel cumprod.  Block = cin (256 blocks), thread = cout (256).
// Kogge-Stone inclusive product scan, 8 steps.  Row 0 forced to 1.
// ---------------------------------------------------------------------------
__global__ void scan_kernel(const float* __restrict__ weight) {
    int cin = blockIdx.x;
    int co  = threadIdx.x;
    __shared__ float sh[CH];
    float v = (co == 0) ? 1.0f : fmaxf(weight[co * CH + cin], 0.0f);
    sh[co] = v;
    __syncthreads();
    #pragma unroll
    for (int off = 1; off < CH; off <<= 1) {
        float t = (co >= off) ? sh[co - off] : 1.0f;
        __syncthreads();
        sh[co] *= t;
        __syncthreads();
    }
    g_scale[co * CH + cin] = sh[co];
}

// ---------------------------------------------------------------------------
// K1b: deterministic compaction (ballot + popc prefix — no atomics).
// Folds scale into the 3x3 weights, padded to 12 floats (3x LDG.128).
// ---------------------------------------------------------------------------
__global__ void compact_kernel(const float* __restrict__ conv_w) {
    int co  = blockIdx.x;
    int cin = threadIdx.x;
    float sc = g_scale[co * CH + cin];
    bool active = (sc != 0.0f);
    unsigned mask = __ballot_sync(0xffffffffu, active);
    int lane = cin & 31, warp = cin >> 5;
    __shared__ int wcnt[8];
    if (lane == 0) wcnt[warp] = __popc(mask);
    __syncthreads();
    int base = 0;
    #pragma unroll
    for (int i = 0; i < 8; i++)
        if (i < warp) base += wcnt[i];
    if (active) {
        int slot = base + __popc(mask & ((1u << lane) - 1u));
        g_cin[co * CH + slot] = cin;
        const float* ws = conv_w + (size_t)(co * CH + cin) * 9;
        float*       wd = g_w    + (size_t)(co * CH + slot) * 12;
        #pragma unroll
        for (int k = 0; k < 9; k++) wd[k] = ws[k] * sc;
        wd[9] = 0.0f; wd[10] = 0.0f; wd[11] = 0.0f;
    }
    if (cin == 0) {
        int t = 0;
        #pragma unroll
        for (int i = 0; i < 8; i++) t += wcnt[i];
        g_count[co] = t;
    }
}

// ---------------------------------------------------------------------------
// K2 (pass 1): direct 3x3 conv over a chunk of the compacted channel list,
// with a double-buffered smem tile (one barrier per slot, next-slot LDGs
// issued under current-slot compute).
// grid = (4 y-tiles, 283 schedule entries, 16 batch), 256 threads.
// Entries y<32 are chunks of couts 0..4 -> write partials (no bias).
// Entries y>=32 are whole couts 5..255 -> write output (+bias) directly;
// empty couts degenerate to a pure bias fill.
// ---------------------------------------------------------------------------
__global__ __launch_bounds__(256) void conv_kernel(const float* __restrict__ in,
                                                   const float* __restrict__ bias,
                                                   float* __restrict__ out) {
    int y  = blockIdx.y;
    int b  = blockIdx.z;
    int y0 = blockIdx.x * TY;
    int tid = threadIdx.x;
    int cx  = tid & 63;
    int ty  = (tid >> 6) << 2;

    // Static schedule-entry -> (cout, nchunks, chunk, partial-slot)
    int co, nck, ch, pslot;
    if      (y < 16) { co = 0;      nck = 16; ch = y;      pslot = y;      }
    else if (y < 24) { co = 1;      nck = 8;  ch = y - 16; pslot = y;      }
    else if (y < 28) { co = 2;      nck = 4;  ch = y - 24; pslot = y;      }
    else if (y < 30) { co = 3;      nck = 2;  ch = y - 28; pslot = y;      }
    else if (y < 32) { co = 4;      nck = 2;  ch = y - 30; pslot = y;      }
    else             { co = y - 27; nck = 1;  ch = 0;      pslot = -1;     }

    int cnt = g_count[co];
    int lo  = ch * cnt / nck;
    int hi  = (ch + 1) * cnt / nck;
    int n   = hi - lo;

    __shared__ float s_tile[2][TY + 2][WW + 2];

    // Permanent zero halo columns (input x = -1 and x = 64), both buffers.
    if (tid < 2 * (TY + 2)) {
        int r = tid >> 1;
        int c = (tid & 1) ? (WW + 1) : 0;
        s_tile[0][r][c] = 0.0f;
        s_tile[1][r][c] = 0.0f;
    }

    // Per-thread fixed tile-fill coordinates (5 strided elements, last guarded).
    int fr[5], fc[5], fgy[5]; bool fp[5];
    #pragma unroll
    for (int i = 0; i < 5; i++) {
        int idx = tid + i * 256;
        fr[i] = idx >> 6;
        fc[i] = idx & 63;
        int gy = y0 - 1 + fr[i];
        fgy[i] = gy;
        fp[i]  = (idx < TILE_ELEMS) && (gy >= 0) && (gy < HH);
    }

    float acc0 = 0.0f, acc1 = 0.0f, acc2 = 0.0f, acc3 = 0.0f;
    float ld[5];
    int cobase = co * CH;

    // Prologue: fetch slot lo into buffer 0.
    if (n > 0) {
        const float* plane = in + (((size_t)b * CH + g_cin[cobase + lo]) << 12);
        #pragma unroll
        for (int i = 0; i < 5; i++)
            ld[i] = fp[i] ? plane[(fgy[i] << 6) + fc[i]] : 0.0f;
        #pragma unroll
        for (int i = 0; i < 5; i++)
            if (tid + i * 256 < TILE_ELEMS) s_tile[0][fr[i]][fc[i] + 1] = ld[i];
    }

    for (int s = 0; s < n; ++s) {
        int cur = s & 1;
        __syncthreads();   // slot s visible in buf[cur]; buf[1-cur] free to refill

        // Issue next slot's global loads early (latency hides under compute).
        bool more = (s + 1 < n);
        if (more) {
            const float* plane = in + (((size_t)b * CH + g_cin[cobase + lo + s + 1]) << 12);
            #pragma unroll
            for (int i = 0; i < 5; i++)
                ld[i] = fp[i] ? plane[(fgy[i] << 6) + fc[i]] : 0.0f;
        }

        const float4* wp = reinterpret_cast<const float4*>(g_w + (size_t)(cobase + lo + s) * 12);
        float4 w0 = __ldg(wp);
        float4 w1 = __ldg(wp + 1);
        float4 w2 = __ldg(wp + 2);

        // 6-row x 3-col register window for this thread's 4-row output strip.
        float v[6][3];
        #pragma unroll
        for (int r = 0; r < 6; r++)
            #pragma unroll
            for (int d = 0; d < 3; d++)
                v[r][d] = s_tile[cur][ty + r][cx + d];

        float wk[9] = {w0.x, w0.y, w0.z, w0.w, w1.x, w1.y, w1.z, w1.w, w2.x};
        #pragma unroll
        for (int dy = 0; dy < 3; dy++) {
            #pragma unroll
            for (int d = 0; d < 3; d++) {
                float wv = wk[dy * 3 + d];
                acc0 = fmaf(wv, v[0 + dy][d], acc0);
                acc1 = fmaf(wv, v[1 + dy][d], acc1);
                acc2 = fmaf(wv, v[2 + dy][d], acc2);
                acc3 = fmaf(wv, v[3 + dy][d], acc3);
            }
        }

        if (more) {
            #pragma unroll
            for (int i = 0; i < 5; i++)
                if (tid + i * 256 < TILE_ELEMS) s_tile[1 - cur][fr[i]][fc[i] + 1] = ld[i];
        }
    }

    int py = y0 + ty;
    if (pslot < 0) {
        // Whole cout: write final output with bias.
        float bv = __ldg(bias + co);
        size_t obase = (((size_t)b * CH + co) << 12) + (size_t)(py << 6) + (size_t)cx;
        out[obase]          = acc0 + bv;
        out[obase + WW]     = acc1 + bv;
        out[obase + 2 * WW] = acc2 + bv;
        out[obase + 3 * WW] = acc3 + bv;
    } else {
        // Chunk of a split cout: write partial (unconditionally, so stale
        // scratch can never leak across graph replays).
        float* p = g_part + ((size_t)pslot * BATCH + b) * (HH * WW) + (py << 6) + cx;
        p[0]      = acc0;
        p[WW]     = acc1;
        p[2 * WW] = acc2;
        p[3 * WW] = acc3;
    }
}

// ---------------------------------------------------------------------------
// K3 (pass 2): reduce partials for the 5 split couts, add bias.
// grid = 80 blocks (co 0..4 x batch 16), 256 threads, 16 px per thread.
// ---------------------------------------------------------------------------
__global__ __launch_bounds__(256) void reduce_kernel(const float* __restrict__ bias,
                                                     float* __restrict__ out) {
    const int nck_t[5]   = {16, 8, 4, 2, 2};
    const int pbase_t[5] = {0, 16, 24, 28, 30};
    int blk = blockIdx.x;
    int co  = blk >> 4;
    int b   = blk & 15;
    int nck = nck_t[co], pbase = pbase_t[co];
    float bv = __ldg(bias + co);
    size_t obase = (((size_t)b * CH + co) << 12);
    for (int px = threadIdx.x; px < HH * WW; px += 256) {
        float s = bv;
        for (int k = 0; k < nck; k++)
            s += g_part[((size_t)(pbase + k) * BATCH + b) * (HH * WW) + px];
        out[obase + px] = s;
    }
}

// ---------------------------------------------------------------------------
// Entry point. Inputs (metadata order): input, conv_w, conv_b, weight.
// Four plain launches: graph-capturable, allocation-free, deterministic.
// ---------------------------------------------------------------------------
extern "C" void kernel_launch(void* const* d_in, const int* in_sizes, int n_in,
                              void* d_out, int out_size) {
    (void)in_sizes; (void)n_in; (void)out_size;
    const float* input  = (const float*)d_in[0];
    const float* conv_w = (const float*)d_in[1];
    const float* conv_b = (const float*)d_in[2];
    const float* weight = (const float*)d_in[3];
    float* out = (float*)d_out;

    scan_kernel<<<CH, CH>>>(weight);
    compact_kernel<<<CH, CH>>>(conv_w);
    dim3 grid(HH / TY, GRID_Y, BATCH);
    conv_kernel<<<grid, 256>>>(input, conv_b, out);
    reduce_kernel<<<5 * BATCH, 256>>>(conv_b, out);
}

// round 5
// speedup vs baseline: 4.4452x; 1.9357x over previous
#include <cuda_runtime.h>
#include <cstdint>

// Problem constants
#define BATCH 16
#define CH    256     // CIN == COUT == 256
#define HH    64
#define WW    64
#define TY    16      // output rows per block tile
#define TROWS (TY + 2)          // 18 tile rows (with halo)
#define ROWF  72                // smem row stride in floats (data at cols 4..67)
#define NV4   (TROWS * 16)      // 288 float4 copies per tile

// Split-cout static schedule: co0->16 chunks, co1->8, co2->4, co3->2, co4->2,
// co5..255 -> 1 chunk.  grid.y = 32 + 251 = 283.
#define NSPLIT_ENTRIES 32
#define GRID_Y 283

// ---------------------------------------------------------------------------
// Scratch (device globals — no runtime allocation allowed)
// ---------------------------------------------------------------------------
__device__ float g_scale[CH * CH];
__device__ int   g_cin  [CH * CH];
__device__ float g_w    [CH * CH * 12];
__device__ int   g_count[CH];
__device__ float g_part [NSPLIT_ENTRIES * BATCH * HH * WW];  // 8 MB partials

// ---------------------------------------------------------------------------
// cp.async helpers (sm_100a LDGSTS path)
// ---------------------------------------------------------------------------
__device__ __forceinline__ void cp_async16(uint32_t saddr, const float* gptr, int src_size) {
    asm volatile("cp.async.ca.shared.global [%0], [%1], 16, %2;\n"
                 :: "r"(saddr), "l"(gptr), "r"(src_size));
}
__device__ __forceinline__ void cp_commit() {
    asm volatile("cp.async.commit_group;\n" ::);
}
template <int N> __device__ __forceinline__ void cp_wait() {
    asm volatile("cp.async.wait_group %0;\n" :: "n"(N));
}

// ---------------------------------------------------------------------------
// K1a: parallel cumprod.  Block = cin (256 blocks), thread = cout (256).
// Kogge-Stone inclusive product scan, 8 steps.  Row 0 forced to 1.
// ---------------------------------------------------------------------------
__global__ void scan_kernel(const float* __restrict__ weight) {
    int cin = blockIdx.x;
    int co  = threadIdx.x;
    __shared__ float sh[CH];
    sh[co] = (co == 0) ? 1.0f : fmaxf(weight[co * CH + cin], 0.0f);
    __syncthreads();
    #pragma unroll
    for (int off = 1; off < CH; off <<= 1) {
        float t = (co >= off) ? sh[co - off] : 1.0f;
        __syncthreads();
        sh[co] *= t;
        __syncthreads();
    }
    g_scale[co * CH + cin] = sh[co];
}

// ---------------------------------------------------------------------------
// K1b: deterministic compaction (ballot + popc prefix — no atomics).
// ---------------------------------------------------------------------------
__global__ void compact_kernel(const float* __restrict__ conv_w) {
    int co  = blockIdx.x;
    int cin = threadIdx.x;
    float sc = g_scale[co * CH + cin];
    bool active = (sc != 0.0f);
    unsigned mask = __ballot_sync(0xffffffffu, active);
    int lane = cin & 31, warp = cin >> 5;
    __shared__ int wcnt[8];
    if (lane == 0) wcnt[warp] = __popc(mask);
    __syncthreads();
    int base = 0;
    #pragma unroll
    for (int i = 0; i < 8; i++)
        if (i < warp) base += wcnt[i];
    if (active) {
        int slot = base + __popc(mask & ((1u << lane) - 1u));
        g_cin[co * CH + slot] = cin;
        const float* ws = conv_w + (size_t)(co * CH + cin) * 9;
        float*       wd = g_w    + (size_t)(co * CH + slot) * 12;
        #pragma unroll
        for (int k = 0; k < 9; k++) wd[k] = ws[k] * sc;
        wd[9] = 0.0f; wd[10] = 0.0f; wd[11] = 0.0f;
    }
    if (cin == 0) {
        int t = 0;
        #pragma unroll
        for (int i = 0; i < 8; i++) t += wcnt[i];
        g_count[co] = t;
    }
}

// ---------------------------------------------------------------------------
// K2 (pass 1): direct 3x3 conv over a chunk of the compacted channel list.
// 4-stage cp.async ring: one __syncthreads per slot, slot s+3's gmem->smem
// copies in flight while slot s computes.  Tile = 18 rows x 64 cols, stored
// at float-col offset 4 of a 72-float row so every 16B copy is aligned.
// Halo columns (3 and 68) are permanently zero.
// ---------------------------------------------------------------------------
__global__ __launch_bounds__(256) void conv_kernel(const float* __restrict__ in,
                                                   const float* __restrict__ bias,
                                                   float* __restrict__ out) {
    int y  = blockIdx.y;
    int b  = blockIdx.z;
    int y0 = blockIdx.x * TY;
    int tid = threadIdx.x;
    int cx  = tid & 63;
    int ty  = (tid >> 6) << 2;

    // Static schedule-entry -> (cout, nchunks, chunk, partial-slot)
    int co, nck, ch, pslot;
    if      (y < 16) { co = 0;      nck = 16; ch = y;      pslot = y; }
    else if (y < 24) { co = 1;      nck = 8;  ch = y - 16; pslot = y; }
    else if (y < 28) { co = 2;      nck = 4;  ch = y - 24; pslot = y; }
    else if (y < 30) { co = 3;      nck = 2;  ch = y - 28; pslot = y; }
    else if (y < 32) { co = 4;      nck = 2;  ch = y - 30; pslot = y; }
    else             { co = y - 27; nck = 1;  ch = 0;      pslot = -1; }

    int cnt = g_count[co];
    int lo  = ch * cnt / nck;
    int n   = (ch + 1) * cnt / nck - lo;
    int cobase = co * CH;

    __shared__ __align__(16) float s_tile[4][TROWS][ROWF];

    float acc0 = 0.0f, acc1 = 0.0f, acc2 = 0.0f, acc3 = 0.0f;
    int py = y0 + ty;

    if (n > 0) {
        // Permanent zero halo columns (float cols 3 and 68) in all 4 buffers.
        if (tid < 4 * TROWS * 2) {
            int buf = tid / (TROWS * 2);
            int rem = tid - buf * (TROWS * 2);
            int r = rem >> 1;
            int c = (rem & 1) ? 68 : 3;
            s_tile[buf][r][c] = 0.0f;
        }

        // Per-thread copy descriptors: idx = tid and tid+256 (<288).
        // idx -> row r = idx>>4, 16B-chunk c4 = idx&15.
        int  r0 = tid >> 4,        c40 = tid & 15;
        int  gy0 = y0 - 1 + r0;
        int  sz0 = (gy0 >= 0 && gy0 < HH) ? 16 : 0;
        long go0 = (long)gy0 * WW + c40 * 4;          // element offset (may be <0; unused if sz=0)
        uint32_t so0 = (uint32_t)__cvta_generic_to_shared(&s_tile[0][r0][4 + c40 * 4]);

        bool has1 = (tid < NV4 - 256);                // 32 threads carry a 2nd copy
        int  r1 = (tid + 256) >> 4,  c41 = (tid + 256) & 15;
        int  gy1 = y0 - 1 + r1;
        int  sz1 = (gy1 >= 0 && gy1 < HH) ? 16 : 0;
        long go1 = (long)gy1 * WW + c41 * 4;
        uint32_t so1 = (uint32_t)__cvta_generic_to_shared(&s_tile[0][r1][4 + c41 * 4]);
        const uint32_t BUFB = TROWS * ROWF * 4;       // bytes per buffer

        // Prologue: issue copy groups for slots 0..min(n,3)-1.
        #pragma unroll
        for (int s = 0; s < 3; ++s) {
            if (s < n) {
                const float* plane = in + (((size_t)b * CH + g_cin[cobase + lo + s]) << 12);
                uint32_t bo = (uint32_t)(s & 3) * BUFB;
                cp_async16(so0 + bo, plane + go0, sz0);
                if (has1) cp_async16(so1 + bo, plane + go1, sz1);
                cp_commit();
            }
        }

        for (int s = 0; s < n; ++s) {
            // Wait until slot s's copy group has landed.
            int rem = n - s - 1;
            if (rem >= 2)      cp_wait<2>();
            else if (rem == 1) cp_wait<1>();
            else               cp_wait<0>();
            __syncthreads();   // slot s visible to all; buffer (s-1)&3 free

            // Issue slot s+3 into buffer (s-1)&3.
            if (s + 3 < n) {
                const float* plane = in + (((size_t)b * CH + g_cin[cobase + lo + s + 3]) << 12);
                uint32_t bo = (uint32_t)((s + 3) & 3) * BUFB;
                cp_async16(so0 + bo, plane + go0, sz0);
                if (has1) cp_async16(so1 + bo, plane + go1, sz1);
                cp_commit();
            }

            const float4* wp = reinterpret_cast<const float4*>(g_w + (size_t)(cobase + lo + s) * 12);
            float4 w0 = __ldg(wp);
            float4 w1 = __ldg(wp + 1);
            float4 w2 = __ldg(wp + 2);

            const float (*tb)[ROWF] = s_tile[s & 3];
            float v[6][3];
            #pragma unroll
            for (int r = 0; r < 6; r++)
                #pragma unroll
                for (int d = 0; d < 3; d++)
                    v[r][d] = tb[ty + r][3 + cx + d];

            float wk[9] = {w0.x, w0.y, w0.z, w0.w, w1.x, w1.y, w1.z, w1.w, w2.x};
            #pragma unroll
            for (int dy = 0; dy < 3; dy++) {
                #pragma unroll
                for (int d = 0; d < 3; d++) {
                    float wv = wk[dy * 3 + d];
                    acc0 = fmaf(wv, v[0 + dy][d], acc0);
                    acc1 = fmaf(wv, v[1 + dy][d], acc1);
                    acc2 = fmaf(wv, v[2 + dy][d], acc2);
                    acc3 = fmaf(wv, v[3 + dy][d], acc3);
                }
            }
        }
    }

    if (pslot < 0) {
        float bv = __ldg(bias + co);
        size_t obase = (((size_t)b * CH + co) << 12) + (size_t)(py << 6) + (size_t)cx;
        out[obase]          = acc0 + bv;
        out[obase + WW]     = acc1 + bv;
        out[obase + 2 * WW] = acc2 + bv;
        out[obase + 3 * WW] = acc3 + bv;
    } else {
        // Unconditional partial write (replay-safe even when n == 0).
        float* p = g_part + ((size_t)pslot * BATCH + b) * (HH * WW) + (py << 6) + cx;
        p[0]      = acc0;
        p[WW]     = acc1;
        p[2 * WW] = acc2;
        p[3 * WW] = acc3;
    }
}

// ---------------------------------------------------------------------------
// K3 (pass 2): reduce partials for the 5 split couts, add bias.
// grid = 320 blocks (co 0..4 x batch 16 x 4 px-chunks), 256 threads,
// one float4 per thread, fully unrolled guarded k-loop (MLP up to 16).
// ---------------------------------------------------------------------------
__global__ __launch_bounds__(256) void reduce_kernel(const float* __restrict__ bias,
                                                     float* __restrict__ out) {
    const int nck_t[5]   = {16, 8, 4, 2, 2};
    const int pbase_t[5] = {0, 16, 24, 28, 30};
    int blk = blockIdx.x;
    int co  = blk >> 6;            // 0..4
    int sub = blk & 63;
    int b   = sub >> 2;            // 0..15
    int q   = sub & 3;             // px-chunk
    int nck = nck_t[co], pbase = pbase_t[co];

    int v4 = q * 256 + threadIdx.x;            // float4 index 0..1023
    float bv = __ldg(bias + co);
    float4 acc = make_float4(bv, bv, bv, bv);

    const float4* part4 = reinterpret_cast<const float4*>(g_part);
    size_t base = ((size_t)pbase * BATCH + b) * (HH * WW / 4) + v4;
    const size_t stride = (size_t)BATCH * (HH * WW / 4);   // one pslot plane (in float4)

    #pragma unroll
    for (int k = 0; k < 16; ++k) {
        if (k < nck) {
            float4 p = part4[base + (size_t)k * stride];
            acc.x += p.x; acc.y += p.y; acc.z += p.z; acc.w += p.w;
        }
    }

    float4* out4 = reinterpret_cast<float4*>(out);
    out4[(((size_t)b * CH + co) << 10) + v4] = acc;
}

// ---------------------------------------------------------------------------
// Entry point. Inputs (metadata order): input, conv_w, conv_b, weight.
// ---------------------------------------------------------------------------
extern "C" void kernel_launch(void* const* d_in, const int* in_sizes, int n_in,
                              void* d_out, int out_size) {
    (void)in_sizes; (void)n_in; (void)out_size;
    const float* input  = (const float*)d_in[0];
    const float* conv_w = (const float*)d_in[1];
    const float* conv_b = (const float*)d_in[2];
    const float* weight = (const float*)d_in[3];
    float* out = (float*)d_out;

    scan_kernel<<<CH, CH>>>(weight);
    compact_kernel<<<CH, CH>>>(conv_w);
    dim3 grid(HH / TY, GRID_Y, BATCH);
    conv_kernel<<<grid, 256>>>(input, conv_b, out);
    reduce_kernel<<<5 * BATCH * 4, 256>>>(conv_b, out);
}

// round 6
// speedup vs baseline: 5.2453x; 1.1800x over previous
#include <cuda_runtime.h>
#include <cstdint>

// Problem constants
#define BATCH 16
#define CH    256
#define HH    64
#define WW    64
#define TROWS 66                 // 64 rows + top/bottom halo
#define ROWF  72                 // smem row stride (floats); data at cols 4..67
#define NBUF  3
#define BUFF  (TROWS * ROWF)     // floats per buffer
#define BUFB  (BUFF * 4)         // bytes per buffer
#define NV4C  (TROWS * 16)       // 1056 float4 copies per tile

// Split schedule: co0->32 chunks, co1->16, co2->8, co3->4, co4->2, rest->1.
#define NSPLIT 62
#define GRID_X (NSPLIT + 251)    // 313 schedule entries

// ---------------------------------------------------------------------------
// Scratch (device globals — no runtime allocation allowed)
// ---------------------------------------------------------------------------
__device__ float g_scale[CH * CH];
__device__ int   g_cin  [CH * CH];
__device__ float g_w    [CH * CH * 12];
__device__ int   g_count[CH];
__device__ float g_part [NSPLIT * BATCH * HH * WW];   // ~16.25 MB partials

// ---------------------------------------------------------------------------
// cp.async helpers
// ---------------------------------------------------------------------------
__device__ __forceinline__ void cp_async16(uint32_t saddr, const float* gptr, int src_size) {
    asm volatile("cp.async.ca.shared.global [%0], [%1], 16, %2;\n"
                 :: "r"(saddr), "l"(gptr), "r"(src_size));
}
__device__ __forceinline__ void cp_commit() {
    asm volatile("cp.async.commit_group;\n" ::);
}
template <int N> __device__ __forceinline__ void cp_wait() {
    asm volatile("cp.async.wait_group %0;\n" :: "n"(N));
}

// ---------------------------------------------------------------------------
// K1a: parallel cumprod (Kogge-Stone, 8 steps). Block = cin, thread = cout.
// ---------------------------------------------------------------------------
__global__ void scan_kernel(const float* __restrict__ weight) {
    int cin = blockIdx.x;
    int co  = threadIdx.x;
    __shared__ float sh[CH];
    sh[co] = (co == 0) ? 1.0f : fmaxf(weight[co * CH + cin], 0.0f);
    __syncthreads();
    #pragma unroll
    for (int off = 1; off < CH; off <<= 1) {
        float t = (co >= off) ? sh[co - off] : 1.0f;
        __syncthreads();
        sh[co] *= t;
        __syncthreads();
    }
    g_scale[co * CH + cin] = sh[co];
}

// ---------------------------------------------------------------------------
// K1b: deterministic compaction (ballot + popc prefix — no atomics).
// ---------------------------------------------------------------------------
__global__ void compact_kernel(const float* __restrict__ conv_w) {
    int co  = blockIdx.x;
    int cin = threadIdx.x;
    float sc = g_scale[co * CH + cin];
    bool active = (sc != 0.0f);
    unsigned mask = __ballot_sync(0xffffffffu, active);
    int lane = cin & 31, warp = cin >> 5;
    __shared__ int wcnt[8];
    if (lane == 0) wcnt[warp] = __popc(mask);
    __syncthreads();
    int base = 0;
    #pragma unroll
    for (int i = 0; i < 8; i++)
        if (i < warp) base += wcnt[i];
    if (active) {
        int slot = base + __popc(mask & ((1u << lane) - 1u));
        g_cin[co * CH + slot] = cin;
        const float* ws = conv_w + (size_t)(co * CH + cin) * 9;
        float*       wd = g_w    + (size_t)(co * CH + slot) * 12;
        #pragma unroll
        for (int k = 0; k < 9; k++) wd[k] = ws[k] * sc;
        wd[9] = 0.0f; wd[10] = 0.0f; wd[11] = 0.0f;
    }
    if (cin == 0) {
        int t = 0;
        #pragma unroll
        for (int i = 0; i < 8; i++) t += wcnt[i];
        g_count[co] = t;
    }
}

// ---------------------------------------------------------------------------
// K2: whole-plane 3x3 conv over a chunk of the compacted channel list.
// grid = (313 entries, 16 batch), 256 threads.  Thread owns a 4x4 output
// micro-tile (rg = tid>>4 row group, cg = tid&15 col group).  3-buffer
// cp.async ring, one __syncthreads per slot, depth-2 lookahead.
// ---------------------------------------------------------------------------
__global__ __launch_bounds__(256) void conv_kernel(const float* __restrict__ in,
                                                   const float* __restrict__ bias,
                                                   float* __restrict__ out) {
    int y   = blockIdx.x;
    int b   = blockIdx.y;
    int tid = threadIdx.x;
    int cg  = tid & 15;
    int rg  = tid >> 4;

    // Static schedule entry -> (cout, nchunks, chunk, partial slot)
    int co, nck, ch, pslot;
    if      (y < 32) { co = 0;      nck = 32; ch = y;      pslot = y;  }
    else if (y < 48) { co = 1;      nck = 16; ch = y - 32; pslot = y;  }
    else if (y < 56) { co = 2;      nck = 8;  ch = y - 48; pslot = y;  }
    else if (y < 60) { co = 3;      nck = 4;  ch = y - 56; pslot = y;  }
    else if (y < 62) { co = 4;      nck = 2;  ch = y - 60; pslot = y;  }
    else             { co = y - 57; nck = 1;  ch = 0;      pslot = -1; }

    int cnt = g_count[co];
    int lo  = ch * cnt / nck;
    int n   = (ch + 1) * cnt / nck - lo;
    int cobase = co * CH;

    extern __shared__ __align__(16) float smem[];   // [NBUF][TROWS][ROWF]

    float acc[4][4] = {};

    if (n > 0) {
        // Permanent zero halo columns (float cols 3 and 68) in all buffers.
        for (int i = tid; i < NBUF * TROWS * 2; i += 256) {
            int buf = i / (TROWS * 2);
            int rem = i - buf * (TROWS * 2);
            int r = rem >> 1;
            int c = (rem & 1) ? 68 : 3;
            smem[buf * BUFF + r * ROWF + c] = 0.0f;
        }

        // Copy descriptors: idx = tid + 256*i, i = 0..3 always valid; i = 4
        // only for tid < 32 (NV4C = 1056).  Row r maps to gy = r - 1;
        // out-of-image rows use src_size = 0 (zero fill).
        uint32_t so[5]; long go[5]; int sz[5];
        #pragma unroll
        for (int i = 0; i < 5; i++) {
            int idx = tid + 256 * i;
            int r = idx >> 4, c4 = idx & 15;
            int gy = r - 1;
            bool valid = (i < 4) || (tid < 32);
            sz[i] = (valid && gy >= 0 && gy < HH) ? 16 : 0;
            go[i] = (long)gy * WW + c4 * 4;
            so[i] = valid ? (uint32_t)__cvta_generic_to_shared(&smem[r * ROWF + 4 + 4 * c4]) : 0u;
        }

        auto issue = [&](int s) {
            const float* plane = in + (((size_t)b * CH + g_cin[cobase + lo + s]) << 12);
            uint32_t bo = (uint32_t)(s % NBUF) * BUFB;
            #pragma unroll
            for (int i = 0; i < 4; i++) cp_async16(so[i] + bo, plane + go[i], sz[i]);
            if (tid < 32) cp_async16(so[4] + bo, plane + go[4], sz[4]);
            cp_commit();
        };

        issue(0);
        if (n > 1) issue(1);

        for (int s = 0; s < n; ++s) {
            if (n - s - 1 >= 1) cp_wait<1>(); else cp_wait<0>();
            __syncthreads();              // slot s visible; buffer (s-1)%3 free

            if (s + 2 < n) issue(s + 2);  // into buffer (s+2)%3 == (s-1)%3

            const float4* wp = reinterpret_cast<const float4*>(g_w + (size_t)(cobase + lo + s) * 12);
            float4 w0 = __ldg(wp);
            float4 w1 = __ldg(wp + 1);
            float4 w2 = __ldg(wp + 2);
            float wk[9] = {w0.x, w0.y, w0.z, w0.w, w1.x, w1.y, w1.z, w1.w, w2.x};

            const float* tb = smem + (s % NBUF) * BUFF;
            #pragma unroll
            for (int r = 0; r < 6; r++) {
                const float* rowp = tb + (4 * rg + r) * ROWF + 4 * cg;
                float4 m = *reinterpret_cast<const float4*>(rowp + 4);
                float vv[6] = {rowp[3], m.x, m.y, m.z, m.w, rowp[8]};
                #pragma unroll
                for (int dy = 0; dy < 3; dy++) {
                    int orow = r - dy;
                    if (orow >= 0 && orow < 4) {
                        #pragma unroll
                        for (int c = 0; c < 4; c++) {
                            acc[orow][c] = fmaf(wk[dy * 3 + 0], vv[c + 0], acc[orow][c]);
                            acc[orow][c] = fmaf(wk[dy * 3 + 1], vv[c + 1], acc[orow][c]);
                            acc[orow][c] = fmaf(wk[dy * 3 + 2], vv[c + 2], acc[orow][c]);
                        }
                    }
                }
            }
        }
    }

    if (pslot < 0) {
        float bv = __ldg(bias + co);
        float4* o4 = reinterpret_cast<float4*>(out) + (((size_t)b * CH + co) << 10);
        #pragma unroll
        for (int r = 0; r < 4; r++)
            o4[(((4 * rg + r)) << 4) + cg] =
                make_float4(acc[r][0] + bv, acc[r][1] + bv, acc[r][2] + bv, acc[r][3] + bv);
    } else {
        // Unconditional partial write (replay-safe even when n == 0).
        float4* p4 = reinterpret_cast<float4*>(g_part) + ((size_t)pslot * BATCH + b) * 1024;
        #pragma unroll
        for (int r = 0; r < 4; r++)
            p4[(((4 * rg + r)) << 4) + cg] =
                make_float4(acc[r][0], acc[r][1], acc[r][2], acc[r][3]);
    }
}

// ---------------------------------------------------------------------------
// K3: reduce partials for the 5 split couts, add bias.
// grid = 5*16*8 = 640 blocks, 128 threads, 1 float4/thread, unrolled guarded
// 32-deep k-loop (MLP up to 32).
// ---------------------------------------------------------------------------
__global__ __launch_bounds__(128) void reduce_kernel(const float* __restrict__ bias,
                                                     float* __restrict__ out) {
    const int nck_t[5]   = {32, 16, 8, 4, 2};
    const int pbase_t[5] = {0, 32, 48, 56, 60};
    int blk = blockIdx.x;
    int co  = blk >> 7;            // 0..4
    int rem = blk & 127;
    int b   = rem >> 3;            // 0..15
    int q   = rem & 7;             // px chunk
    int nck = nck_t[co], pbase = pbase_t[co];

    int v4 = q * 128 + threadIdx.x;          // 0..1023 float4 index
    float bv = __ldg(bias + co);
    float4 acc = make_float4(bv, bv, bv, bv);

    const float4* part4 = reinterpret_cast<const float4*>(g_part);
    size_t base = ((size_t)pbase * BATCH + b) * 1024 + v4;
    const size_t stride = (size_t)BATCH * 1024;

    #pragma unroll
    for (int k = 0; k < 32; ++k) {
        if (k < nck) {
            float4 p = part4[base + (size_t)k * stride];
            acc.x += p.x; acc.y += p.y; acc.z += p.z; acc.w += p.w;
        }
    }

    reinterpret_cast<float4*>(out)[(((size_t)b * CH + co) << 10) + v4] = acc;
}

// ---------------------------------------------------------------------------
// Entry point. Inputs (metadata order): input, conv_w, conv_b, weight.
// ---------------------------------------------------------------------------
extern "C" void kernel_launch(void* const* d_in, const int* in_sizes, int n_in,
                              void* d_out, int out_size) {
    (void)in_sizes; (void)n_in; (void)out_size;
    const float* input  = (const float*)d_in[0];
    const float* conv_w = (const float*)d_in[1];
    const float* conv_b = (const float*)d_in[2];
    const float* weight = (const float*)d_in[3];
    float* out = (float*)d_out;

    const int dyn_smem = NBUF * BUFB;   // 57024 bytes
    cudaFuncSetAttribute(conv_kernel, cudaFuncAttributeMaxDynamicSharedMemorySize, dyn_smem);

    scan_kernel<<<CH, CH>>>(weight);
    compact_kernel<<<CH, CH>>>(conv_w);
    dim3 grid(GRID_X, BATCH);
    conv_kernel<<<grid, 256, dyn_smem>>>(input, conv_b, out);
    reduce_kernel<<<5 * BATCH * 8, 128>>>(conv_b, out);
}

// round 7
// speedup vs baseline: 5.4339x; 1.0359x over previous
#include <cuda_runtime.h>
#include <cstdint>

// Problem constants
#define BATCH 16
#define CH    256
#define HH    64
#define WW    64
#define TROWS 66                 // 64 rows + top/bottom halo
#define ROWF  72                 // smem row stride (floats); data at cols 4..67
#define NBUF  2
#define BUFF  (TROWS * ROWF)     // floats per buffer
#define BUFB  (BUFF * 4)         // bytes per buffer (19008)
#define NV4C  (TROWS * 16)       // 1056 float4 copies per tile

// Split schedule: co0->16 chunks, co1->8, co2->4, co3->2, co4->2, rest->1.
#define NSPLIT 32
#define GRID_X (NSPLIT + 251)    // 283 schedule entries

// ---------------------------------------------------------------------------
// Scratch (device globals — no runtime allocation allowed)
// ---------------------------------------------------------------------------
__device__ float g_scale[CH * CH];
__device__ int   g_cin  [CH * CH];
__device__ float g_w    [CH * CH * 12];
__device__ int   g_count[CH];
__device__ float g_part [NSPLIT * BATCH * HH * WW];   // 8 MB partials

// ---------------------------------------------------------------------------
// cp.async helpers
// ---------------------------------------------------------------------------
__device__ __forceinline__ void cp_async16(uint32_t saddr, const float* gptr, int src_size) {
    asm volatile("cp.async.ca.shared.global [%0], [%1], 16, %2;\n"
                 :: "r"(saddr), "l"(gptr), "r"(src_size));
}
__device__ __forceinline__ void cp_commit() {
    asm volatile("cp.async.commit_group;\n" ::);
}
template <int N> __device__ __forceinline__ void cp_wait() {
    asm volatile("cp.async.wait_group %0;\n" :: "n"(N));
}

// ---------------------------------------------------------------------------
// K1a: parallel cumprod (Kogge-Stone, 8 steps). Block = cin, thread = cout.
// ---------------------------------------------------------------------------
__global__ void scan_kernel(const float* __restrict__ weight) {
    int cin = blockIdx.x;
    int co  = threadIdx.x;
    __shared__ float sh[CH];
    sh[co] = (co == 0) ? 1.0f : fmaxf(weight[co * CH + cin], 0.0f);
    __syncthreads();
    #pragma unroll
    for (int off = 1; off < CH; off <<= 1) {
        float t = (co >= off) ? sh[co - off] : 1.0f;
        __syncthreads();
        sh[co] *= t;
        __syncthreads();
    }
    g_scale[co * CH + cin] = sh[co];
}

// ---------------------------------------------------------------------------
// K1b: deterministic compaction (ballot + popc prefix — no atomics).
// ---------------------------------------------------------------------------
__global__ void compact_kernel(const float* __restrict__ conv_w) {
    int co  = blockIdx.x;
    int cin = threadIdx.x;
    float sc = g_scale[co * CH + cin];
    bool active = (sc != 0.0f);
    unsigned mask = __ballot_sync(0xffffffffu, active);
    int lane = cin & 31, warp = cin >> 5;
    __shared__ int wcnt[8];
    if (lane == 0) wcnt[warp] = __popc(mask);
    __syncthreads();
    int base = 0;
    #pragma unroll
    for (int i = 0; i < 8; i++)
        if (i < warp) base += wcnt[i];
    if (active) {
        int slot = base + __popc(mask & ((1u << lane) - 1u));
        g_cin[co * CH + slot] = cin;
        const float* ws = conv_w + (size_t)(co * CH + cin) * 9;
        float*       wd = g_w    + (size_t)(co * CH + slot) * 12;
        #pragma unroll
        for (int k = 0; k < 9; k++) wd[k] = ws[k] * sc;
        wd[9] = 0.0f; wd[10] = 0.0f; wd[11] = 0.0f;
    }
    if (cin == 0) {
        int t = 0;
        #pragma unroll
        for (int i = 0; i < 8; i++) t += wcnt[i];
        g_count[co] = t;
    }
}

// ---------------------------------------------------------------------------
// K2: whole-plane 3x3 conv over a chunk of the compacted channel list.
// grid = (283 entries, 16 batch), 256 threads.  Thread owns a 4x4 output
// micro-tile.  2-buffer cp.async ring (38KB smem -> ~5 blocks/SM), one
// __syncthreads per slot, depth-1 lookahead.
// ---------------------------------------------------------------------------
__global__ __launch_bounds__(256, 5) void conv_kernel(const float* __restrict__ in,
                                                      const float* __restrict__ bias,
                                                      float* __restrict__ out) {
    int y   = blockIdx.x;
    int b   = blockIdx.y;
    int tid = threadIdx.x;
    int cg  = tid & 15;
    int rg  = tid >> 4;

    // Static schedule entry -> (cout, nchunks, chunk, partial slot)
    int co, nck, ch, pslot;
    if      (y < 16) { co = 0;      nck = 16; ch = y;      pslot = y;  }
    else if (y < 24) { co = 1;      nck = 8;  ch = y - 16; pslot = y;  }
    else if (y < 28) { co = 2;      nck = 4;  ch = y - 24; pslot = y;  }
    else if (y < 30) { co = 3;      nck = 2;  ch = y - 28; pslot = y;  }
    else if (y < 32) { co = 4;      nck = 2;  ch = y - 30; pslot = y;  }
    else             { co = y - 27; nck = 1;  ch = 0;      pslot = -1; }

    int cnt = g_count[co];
    int lo  = ch * cnt / nck;
    int n   = (ch + 1) * cnt / nck - lo;
    int cobase = co * CH;

    extern __shared__ __align__(16) float smem[];   // [NBUF][TROWS][ROWF]

    float acc[4][4] = {};

    if (n > 0) {
        // Permanent zero halo columns (float cols 3 and 68) in both buffers.
        for (int i = tid; i < NBUF * TROWS * 2; i += 256) {
            int buf = i / (TROWS * 2);
            int rem = i - buf * (TROWS * 2);
            int r = rem >> 1;
            int c = (rem & 1) ? 68 : 3;
            smem[buf * BUFF + r * ROWF + c] = 0.0f;
        }

        // Copy descriptors: idx = tid + 256*i, i = 0..3 always valid; i = 4
        // only for tid < 32 (NV4C = 1056).  Row r -> gy = r - 1; out-of-image
        // rows use src_size = 0 (zero fill).  32-bit offsets to save regs.
        uint32_t so[5]; int go[5]; int sz[5];
        #pragma unroll
        for (int i = 0; i < 5; i++) {
            int idx = tid + 256 * i;
            int r = idx >> 4, c4 = idx & 15;
            int gy = r - 1;
            bool valid = (i < 4) || (tid < 32);
            sz[i] = (valid && gy >= 0 && gy < HH) ? 16 : 0;
            go[i] = gy * WW + c4 * 4;
            so[i] = valid ? (uint32_t)__cvta_generic_to_shared(&smem[r * ROWF + 4 + 4 * c4]) : 0u;
        }

        auto issue = [&](int s) {
            const float* plane = in + (((size_t)b * CH + g_cin[cobase + lo + s]) << 12);
            uint32_t bo = (uint32_t)(s & 1) * BUFB;
            #pragma unroll
            for (int i = 0; i < 4; i++) cp_async16(so[i] + bo, plane + go[i], sz[i]);
            if (tid < 32) cp_async16(so[4] + bo, plane + go[4], sz[4]);
            cp_commit();
        };

        issue(0);

        for (int s = 0; s < n; ++s) {
            cp_wait<0>();                 // group s landed (only one in flight)
            __syncthreads();              // visible to all; other buffer free

            if (s + 1 < n) issue(s + 1);  // into buffer (s+1)&1

            const float4* wp = reinterpret_cast<const float4*>(g_w + (size_t)(cobase + lo + s) * 12);
            float4 w0 = __ldg(wp);
            float4 w1 = __ldg(wp + 1);
            float4 w2 = __ldg(wp + 2);
            float wk[9] = {w0.x, w0.y, w0.z, w0.w, w1.x, w1.y, w1.z, w1.w, w2.x};

            const float* tb = smem + (s & 1) * BUFF;
            #pragma unroll
            for (int r = 0; r < 6; r++) {
                const float* rowp = tb + (4 * rg + r) * ROWF + 4 * cg;
                float4 m = *reinterpret_cast<const float4*>(rowp + 4);
                float vv[6] = {rowp[3], m.x, m.y, m.z, m.w, rowp[8]};
                #pragma unroll
                for (int dy = 0; dy < 3; dy++) {
                    int orow = r - dy;
                    if (orow >= 0 && orow < 4) {
                        #pragma unroll
                        for (int c = 0; c < 4; c++) {
                            acc[orow][c] = fmaf(wk[dy * 3 + 0], vv[c + 0], acc[orow][c]);
                            acc[orow][c] = fmaf(wk[dy * 3 + 1], vv[c + 1], acc[orow][c]);
                            acc[orow][c] = fmaf(wk[dy * 3 + 2], vv[c + 2], acc[orow][c]);
                        }
                    }
                }
            }
        }
    }

    if (pslot < 0) {
        float bv = __ldg(bias + co);
        float4* o4 = reinterpret_cast<float4*>(out) + (((size_t)b * CH + co) << 10);
        #pragma unroll
        for (int r = 0; r < 4; r++)
            o4[(((4 * rg + r)) << 4) + cg] =
                make_float4(acc[r][0] + bv, acc[r][1] + bv, acc[r][2] + bv, acc[r][3] + bv);
    } else {
        // Unconditional partial write (replay-safe even when n == 0).
        float4* p4 = reinterpret_cast<float4*>(g_part) + ((size_t)pslot * BATCH + b) * 1024;
        #pragma unroll
        for (int r = 0; r < 4; r++)
            p4[(((4 * rg + r)) << 4) + cg] =
                make_float4(acc[r][0], acc[r][1], acc[r][2], acc[r][3]);
    }
}

// ---------------------------------------------------------------------------
// K3: reduce partials for the 5 split couts, add bias.
// grid = 5*16*8 = 640 blocks, 128 threads, 1 float4/thread, unrolled guarded
// 16-deep k-loop (MLP up to 16).
// ---------------------------------------------------------------------------
__global__ __launch_bounds__(128) void reduce_kernel(const float* __restrict__ bias,
                                                     float* __restrict__ out) {
    const int nck_t[5]   = {16, 8, 4, 2, 2};
    const int pbase_t[5] = {0, 16, 24, 28, 30};
    int blk = blockIdx.x;
    int co  = blk >> 7;            // 0..4
    int rem = blk & 127;
    int b   = rem >> 3;            // 0..15
    int q   = rem & 7;             // px chunk
    int nck = nck_t[co], pbase = pbase_t[co];

    int v4 = q * 128 + threadIdx.x;          // 0..1023 float4 index
    float bv = __ldg(bias + co);
    float4 acc = make_float4(bv, bv, bv, bv);

    const float4* part4 = reinterpret_cast<const float4*>(g_part);
    size_t base = ((size_t)pbase * BATCH + b) * 1024 + v4;
    const size_t stride = (size_t)BATCH * 1024;

    #pragma unroll
    for (int k = 0; k < 16; ++k) {
        if (k < nck) {
            float4 p = part4[base + (size_t)k * stride];
            acc.x += p.x; acc.y += p.y; acc.z += p.z; acc.w += p.w;
        }
    }

    reinterpret_cast<float4*>(out)[(((size_t)b * CH + co) << 10) + v4] = acc;
}

// ---------------------------------------------------------------------------
// Entry point. Inputs (metadata order): input, conv_w, conv_b, weight.
// ---------------------------------------------------------------------------
extern "C" void kernel_launch(void* const* d_in, const int* in_sizes, int n_in,
                              void* d_out, int out_size) {
    (void)in_sizes; (void)n_in; (void)out_size;
    const float* input  = (const float*)d_in[0];
    const float* conv_w = (const float*)d_in[1];
    const float* conv_b = (const float*)d_in[2];
    const float* weight = (const float*)d_in[3];
    float* out = (float*)d_out;

    const int dyn_smem = NBUF * BUFB;   // 38016 bytes
    cudaFuncSetAttribute(conv_kernel, cudaFuncAttributeMaxDynamicSharedMemorySize, dyn_smem);

    scan_kernel<<<CH, CH>>>(weight);
    compact_kernel<<<CH, CH>>>(conv_w);
    dim3 grid(GRID_X, BATCH);
    conv_kernel<<<grid, 256, dyn_smem>>>(input, conv_b, out);
    reduce_kernel<<<5 * BATCH * 8, 128>>>(conv_b, out);
}